// round 17
// baseline (speedup 1.0000x reference)
#include <cuda_runtime.h>
#include <cuda_bf16.h>

#define HASH_SIZE 256
#define OFFSET_SIZE 64

// L2 evict-last policy for the 3MB offset table (hot, reused every query).
// A/B history (settled): hash gather must use DEFAULT eviction — evict_first,
// evict_last, and .cv all regressed; offset table benefits from evict_last.
__device__ __forceinline__ long long make_evict_last_policy() {
    long long p;
    asm("createpolicy.fractional.L2::evict_last.b64 %0, 1.0;" : "=l"(p));
    return p;
}

__device__ __forceinline__ int ldg_hint_s32(const int* ptr, long long pol) {
    int v;
    asm volatile("ld.global.L2::cache_hint.s32 %0, [%1], %2;"
                 : "=r"(v) : "l"(ptr), "l"(pol));
    return v;
}

// Single 256-bit hash-row gather, default eviction: one L1tex request per
// 32B row (R16-verified best hash-load form).
__device__ __forceinline__ void ldg_row_v8(const void* ptr, float4& a, float4& b) {
    asm volatile(
        "ld.global.L2::evict_normal.v8.b32 {%0,%1,%2,%3,%4,%5,%6,%7}, [%8];"
        : "=f"(a.x), "=f"(a.y), "=f"(a.z), "=f"(a.w),
          "=f"(b.x), "=f"(b.y), "=f"(b.z), "=f"(b.w)
        : "l"(ptr));
}

__global__ __launch_bounds__(256) void psh_kernel(
    const int*    __restrict__ coords,       // [N,3] int32
    const float*  __restrict__ hash_table,   // [256,256,256,8] f32
    const int*    __restrict__ offset_table, // [64,64,64,3] int32
    const float*  __restrict__ m0,           // [3]
    const float*  __restrict__ m1,           // [3]
    float4*       __restrict__ out,          // [N,8] f32 as float4 pairs
    int n)
{
    const float m0x = m0[0], m0y = m0[1], m0z = m0[2];
    const float m1x = m1[0], m1y = m1[1], m1z = m1[2];

    int i = blockIdx.x * blockDim.x + threadIdx.x;
    if (i >= n) return;

    const long long pol = make_evict_last_policy();

    // --- coords: dense, read-once -> streaming loads ---
    const int c0 = __ldcs(&coords[3 * i + 0]);
    const int c1 = __ldcs(&coords[3 * i + 1]);
    const int c2 = __ldcs(&coords[3 * i + 2]);

    // --- offset-table index: (int)(c * m1) & 63 (& == floor-mod for pow2) ---
    const int o0 = ((int)((float)c0 * m1x)) & (OFFSET_SIZE - 1);
    const int o1 = ((int)((float)c1 * m1y)) & (OFFSET_SIZE - 1);
    const int o2 = ((int)((float)c2 * m1z)) & (OFFSET_SIZE - 1);
    const int obase = ((((o0 << 6) | o1) << 6) | o2) * 3;

    // --- offset gather: 3MB table, L2-resident under evict_last ---
    const int f0 = ldg_hint_s32(&offset_table[obase + 0], pol);
    const int f1 = ldg_hint_s32(&offset_table[obase + 1], pol);
    const int f2 = ldg_hint_s32(&offset_table[obase + 2], pol);

    // --- hash index: ((int)(c * m0) + off) & 255 ---
    const int h0 = (((int)((float)c0 * m0x)) + f0) & (HASH_SIZE - 1);
    const int h1 = (((int)((float)c1 * m0y)) + f1) & (HASH_SIZE - 1);
    const int h2 = (((int)((float)c2 * m0z)) + f2) & (HASH_SIZE - 1);

    const long long row = (long long)((((h0 << 8) | h1) << 8) | h2);

    // --- hash gather: one 256-bit request, default eviction ---
    float4 a, b;
    ldg_row_v8((const char*)hash_table + row * 32, a, b);

    // --- output: write-once -> streaming stores ---
    const long long ob = 2ll * i;
    __stcs(&out[ob + 0], a);
    __stcs(&out[ob + 1], b);
}

extern "C" void kernel_launch(void* const* d_in, const int* in_sizes, int n_in,
                              void* d_out, int out_size) {
    const int*   coords       = (const int*)d_in[0];
    const float* hash_table   = (const float*)d_in[1];
    const int*   offset_table = (const int*)d_in[2];
    const float* m0           = (const float*)d_in[3];
    const float* m1           = (const float*)d_in[4];
    float4*      out          = (float4*)d_out;

    const int n = in_sizes[0] / 3;
    const int threads = 256;
    const int blocks = (n + threads - 1) / threads;
    psh_kernel<<<blocks, threads>>>(coords, hash_table, offset_table, m0, m1, out, n);
}